// round 15
// baseline (speedup 1.0000x reference)
#include <cuda_runtime.h>
#include <cuda_fp16.h>
#include <stdint.h>

// NCA step via fp16 mma.sync.m16n8k16, warp-standalone chain, 32 px/warp, 2 passes.
// R15: epilogue staged through warp-private smem dxw (aliased over dead halo xh):
// conflict-free STS (pitch 20), conflict-free LDS.128, flat coalesced LDG/STG.128.
// 47.8 KB smem, 4 CTAs/SM.

#define HW   256
#define CH   16
#define TW   32
#define TH   8
#define NPIX 256
#define YPP  264      // u32 pitch for packed ys rows
#define XC2  340      // u32 pitch for fp16 halo rows xh[8][10*34]
#define DXP  20       // dxw fp32 pixel pitch (conflict-free STS)

// u32-unit offsets
#define OFF_YS   0          // 24 pair-rows * 264 = 6336
#define OFF_XH   6336       // 8 * 340 = 2720 ; dxw (8 warps * 320 = 2560) aliases after stencil
#define OFF_WF1  9056       // 1536
#define OFF_WF2  10592      // 1024
#define OFF_WF3  11616      // 256
#define OFF_B1   11872
#define OFF_B2   11936
#define OFF_B3   11968
#define OFF_MS   11984
#define SMEM_U32 12240
#define SMEM_BYTES (SMEM_U32 * 4)

static_assert(OFF_XH  == OFF_YS + 24 * YPP, "ys");
static_assert(8 * 16 * DXP <= 8 * XC2, "dxw fits in xh region");
static_assert(OFF_WF1 == OFF_XH + 8 * XC2, "xh");
static_assert(OFF_WF2 == OFF_WF1 + 1536, "wf1");
static_assert(OFF_WF3 == OFF_WF2 + 1024, "wf2");
static_assert(OFF_B1  == OFF_WF3 + 256, "wf3");
static_assert(OFF_MS + NPIX == SMEM_U32, "total");
static_assert(4 * SMEM_BYTES <= 227 * 1024, "4 CTA/SM smem");

__device__ __forceinline__ float tanh_fast(float v) {
    float y;
    asm("tanh.approx.f32 %0, %1;" : "=f"(y) : "f"(v));
    return y;
}
__device__ __forceinline__ uint32_t pack2h(float a, float b) {
    __half2 h = __floats2half2_rn(a, b);       // a -> low half
    return *(uint32_t*)&h;
}
__device__ __forceinline__ uint32_t movm_t(uint32_t s) {
    uint32_t d;
    asm("movmatrix.sync.aligned.m8n8.trans.b16 %0, %1;" : "=r"(d) : "r"(s));
    return d;
}
__device__ __forceinline__ void mma_f16(float& c0, float& c1, float& c2, float& c3,
                                        uint32_t a0, uint32_t a1, uint32_t a2, uint32_t a3,
                                        uint32_t b0, uint32_t b1)
{
    asm volatile(
        "mma.sync.aligned.m16n8k16.row.col.f32.f16.f16.f32 "
        "{%0,%1,%2,%3},{%4,%5,%6,%7},{%8,%9},{%0,%1,%2,%3};"
        : "+f"(c0), "+f"(c1), "+f"(c2), "+f"(c3)
        : "r"(a0), "r"(a1), "r"(a2), "r"(a3), "r"(b0), "r"(b1));
}

// Stage weights [K=KT*16][D] (fp32, d-contiguous) into fragment order.
template<int D, int KT>
__device__ __forceinline__ void stage_w(const float* __restrict__ w, uint32_t* dst, int tid)
{
    #pragma unroll 1
    for (int p = tid; p < 8 * KT * D; p += 256) {
        int kp = p / D, d = p % D;
        int kt = kp >> 3, kl = kp & 7;
        int t = kl & 3, khalf = kl >> 2;
        int dt = d >> 4, g = d & 7, rhi = (d >> 3) & 1;
        int reg = khalf * 2 + rhi, lane = g * 4 + t;
        float lo = w[(2 * kp) * D + d];
        float hi = w[(2 * kp + 1) * D + d];
        dst[((dt * KT + kt) * 32 + lane) * 4 + reg] = pack2h(lo, hi);
    }
}

__global__ __launch_bounds__(256, 4)
void nca_step_kernel(const float* __restrict__ x,
                     const float* __restrict__ w1, const float* __restrict__ b1,
                     const float* __restrict__ w2, const float* __restrict__ b2,
                     const float* __restrict__ w3, const float* __restrict__ b3,
                     const uint32_t* __restrict__ mask,
                     float* __restrict__ out)
{
    extern __shared__ uint32_t smu[];
    uint32_t* ysU = smu + OFF_YS;
    uint32_t* xh  = smu + OFF_XH;
    uint32_t* wf1 = smu + OFF_WF1;
    uint32_t* wf2 = smu + OFF_WF2;
    uint32_t* wf3 = smu + OFF_WF3;
    float*    b1s = (float*)(smu + OFF_B1);
    float*    b2s = (float*)(smu + OFF_B2);
    float*    b3s = (float*)(smu + OFF_B3);
    float*    ms  = (float*)(smu + OFF_MS);

    const int tid = threadIdx.x;
    const int bx = blockIdx.x, by = blockIdx.y, bb = blockIdx.z;
    const int y0 = by * TH, x0 = bx * TW;

    // ---------------- phase 0: weight fragments / biases / mask / fp16 halo ----------------
    stage_w<64, 3>(w1, wf1, tid);
    stage_w<32, 4>(w2, wf2, tid);
    stage_w<16, 2>(w3, wf3, tid);

    if (tid < 64)       b1s[tid] = b1[tid];
    else if (tid < 96)  b2s[tid - 64] = b2[tid - 64];
    else if (tid < 112) b3s[tid - 96] = b3[tid - 96];

    {   // mask: pixel p = tid (py = tid>>5, xx = tid&31)
        int py = tid >> 5, xx = tid & 31;
        uint32_t w = mask[((size_t)bb * HW + (y0 + py)) * HW + (x0 + xx)];
        ms[tid] = (w != 0u) ? 1.f : 0.f;
    }

    {   // halo 10x34, fp16 channel-pair packed: xh[cp][r*34+cc], zero-pad outside
        const float* xb = x + (size_t)bb * HW * HW * CH;
        const int gy0 = y0 - 1, gx0 = x0 - 1;
        for (int i = tid; i < 10 * 34 * 4; i += 256) {
            int q = i & 3, pix = i >> 2;
            int r = pix / 34, cc = pix - r * 34;
            int gr = gy0 + r, gc = gx0 + cc;
            float4 v = make_float4(0.f, 0.f, 0.f, 0.f);
            if ((unsigned)gr < HW && (unsigned)gc < HW)
                v = *(const float4*)&xb[((size_t)gr * HW + gc) * CH + q * 4];
            int base = r * 34 + cc;
            xh[(2 * q + 0) * XC2 + base] = pack2h(v.x, v.y);
            xh[(2 * q + 1) * XC2 + base] = pack2h(v.z, v.w);
        }
    }
    __syncthreads();

    const int lane = tid & 31, warp = tid >> 5;

    // ---------------- phase 1: half2 stencil -> ys (warp = channel pair, lane = column) ----------------
    {
        const __half2* xc = (const __half2*)(xh + warp * XC2);
        const int xx = lane;
        const __half2 two    = __floats2half2_rn(2.f, 2.f);
        const __half2 eighth = __floats2half2_rn(0.125f, 0.125f);
        __half2 r0a = xc[xx],      r0b = xc[xx + 1],      r0c = xc[xx + 2];
        __half2 r1a = xc[34 + xx], r1b = xc[34 + xx + 1], r1c = xc[34 + xx + 2];
        const int m = warp;   // channel pair index
        #pragma unroll
        for (int py = 0; py < TH; py++) {
            const __half2* row2 = xc + (py + 2) * 34 + xx;
            __half2 r2a = row2[0], r2b = row2[1], r2c = row2[2];
            __half2 gx2 = __hmul2(__hadd2(__hadd2(__hsub2(r0c, r0a), __hsub2(r2c, r2a)),
                                          __hmul2(two, __hsub2(r1c, r1a))), eighth);
            __half2 gy2 = __hmul2(__hadd2(__hadd2(__hsub2(r2a, r0a), __hsub2(r2c, r0c)),
                                          __hmul2(two, __hsub2(r2b, r0b))), eighth);
            uint32_t I2u  = *(uint32_t*)&r1b;
            uint32_t gx2u = *(uint32_t*)&gx2;
            uint32_t gy2u = *(uint32_t*)&gy2;
            int p = py * 32 + xx;
            ysU[(3 * m + 0) * YPP + p] = __byte_perm(I2u,  gx2u, 0x5410);  // (I_e , gx_e)
            ysU[(3 * m + 1) * YPP + p] = __byte_perm(gy2u, I2u,  0x7610);  // (gy_e, I_o )
            ysU[(3 * m + 2) * YPP + p] = __byte_perm(gx2u, gy2u, 0x7632);  // (gx_o, gy_o)
            r0a = r1a; r0b = r1b; r0c = r1c;
            r1a = r2a; r1b = r2b; r1c = r2c;
        }
    }
    __syncthreads();   // after this, xh is dead -> dxw may alias it

    // ---------------- warp-standalone GEMM chain: 32 px per warp, 2 passes of 16 px ----------------
    const int g = lane >> 2, t = lane & 3;
    const int px0 = warp * 32;
    float* dxw = (float*)(smu + OFF_XH) + warp * (16 * DXP);
    const size_t rowoff = (((size_t)bb * HW + (y0 + warp)) * HW + x0) * CH;
    float* orow = out + rowoff;
    const float* xrow = x + rowoff;

    #pragma unroll
    for (int half = 0; half < 2; half++) {
        const int pxh = px0 + half * 16;

        // GEMM1: h1 = tanh(W1^T @ ys + b1) -> h1B[kt=4][nt=2][2]
        uint32_t h1B[4][2][2];
        {
            uint32_t ysB[3][2][2];
            #pragma unroll
            for (int kt = 0; kt < 3; kt++)
                #pragma unroll
                for (int nt = 0; nt < 2; nt++) {
                    ysB[kt][nt][0] = ysU[(8 * kt + t) * YPP + pxh + nt * 8 + g];
                    ysB[kt][nt][1] = ysU[(8 * kt + t + 4) * YPP + pxh + nt * 8 + g];
                }
            #pragma unroll
            for (int mt = 0; mt < 4; mt++) {
                uint4 A0 = *(const uint4*)&wf1[((mt * 3 + 0) * 32 + lane) * 4];
                uint4 A1 = *(const uint4*)&wf1[((mt * 3 + 1) * 32 + lane) * 4];
                uint4 A2 = *(const uint4*)&wf1[((mt * 3 + 2) * 32 + lane) * 4];
                const float bl = b1s[mt * 16 + g], bh = b1s[mt * 16 + g + 8];
                #pragma unroll
                for (int nt = 0; nt < 2; nt++) {
                    float c0 = bl, c1 = bl, c2 = bh, c3 = bh;
                    mma_f16(c0, c1, c2, c3, A0.x, A0.y, A0.z, A0.w, ysB[0][nt][0], ysB[0][nt][1]);
                    mma_f16(c0, c1, c2, c3, A1.x, A1.y, A1.z, A1.w, ysB[1][nt][0], ysB[1][nt][1]);
                    mma_f16(c0, c1, c2, c3, A2.x, A2.y, A2.z, A2.w, ysB[2][nt][0], ysB[2][nt][1]);
                    h1B[mt][nt][0] = movm_t(pack2h(tanh_fast(c0), tanh_fast(c1)));
                    h1B[mt][nt][1] = movm_t(pack2h(tanh_fast(c2), tanh_fast(c3)));
                }
            }
        }

        // GEMM2: h2 = tanh(W2^T @ h1 + b2) -> h2B[kt=2][nt=2][2]
        uint32_t h2B[2][2][2];
        #pragma unroll
        for (int mt = 0; mt < 2; mt++) {
            uint4 A0 = *(const uint4*)&wf2[((mt * 4 + 0) * 32 + lane) * 4];
            uint4 A1 = *(const uint4*)&wf2[((mt * 4 + 1) * 32 + lane) * 4];
            uint4 A2 = *(const uint4*)&wf2[((mt * 4 + 2) * 32 + lane) * 4];
            uint4 A3 = *(const uint4*)&wf2[((mt * 4 + 3) * 32 + lane) * 4];
            const float bl = b2s[mt * 16 + g], bh = b2s[mt * 16 + g + 8];
            #pragma unroll
            for (int nt = 0; nt < 2; nt++) {
                float c0 = bl, c1 = bl, c2 = bh, c3 = bh;
                mma_f16(c0, c1, c2, c3, A0.x, A0.y, A0.z, A0.w, h1B[0][nt][0], h1B[0][nt][1]);
                mma_f16(c0, c1, c2, c3, A1.x, A1.y, A1.z, A1.w, h1B[1][nt][0], h1B[1][nt][1]);
                mma_f16(c0, c1, c2, c3, A2.x, A2.y, A2.z, A2.w, h1B[2][nt][0], h1B[2][nt][1]);
                mma_f16(c0, c1, c2, c3, A3.x, A3.y, A3.z, A3.w, h1B[3][nt][0], h1B[3][nt][1]);
                h2B[mt][nt][0] = movm_t(pack2h(tanh_fast(c0), tanh_fast(c1)));
                h2B[mt][nt][1] = movm_t(pack2h(tanh_fast(c2), tanh_fast(c3)));
            }
        }

        // GEMM3: dx = W3^T @ h2 + b3 -> dxw (conflict-free STS, pitch 20)
        {
            uint4 A0 = *(const uint4*)&wf3[(0 * 32 + lane) * 4];
            uint4 A1 = *(const uint4*)&wf3[(1 * 32 + lane) * 4];
            const float bl = b3s[g], bh = b3s[g + 8];
            #pragma unroll
            for (int nt = 0; nt < 2; nt++) {
                float c0 = bl, c1 = bl, c2 = bh, c3 = bh;
                mma_f16(c0, c1, c2, c3, A0.x, A0.y, A0.z, A0.w, h2B[0][nt][0], h2B[0][nt][1]);
                mma_f16(c0, c1, c2, c3, A1.x, A1.y, A1.z, A1.w, h2B[1][nt][0], h2B[1][nt][1]);
                const int pl0 = nt * 8 + 2 * t, pl1 = pl0 + 1;   // pass-local pixel 0..15
                dxw[pl0 * DXP + g]     = c0;
                dxw[pl1 * DXP + g]     = c1;
                dxw[pl0 * DXP + g + 8] = c2;
                dxw[pl1 * DXP + g + 8] = c3;
            }
        }
        __syncwarp();

        // Epilogue: out = x + dx*mask, flat coalesced 1KB pass-region.
        // lane -> (px = lane&7 and 8+(lane&7), quarter q = lane>>3): conflict-free LDS.128.
        {
            const int pxa = lane & 7, q = lane >> 3;
            float4 da = *(const float4*)&dxw[pxa * DXP + q * 4];
            float4 db = *(const float4*)&dxw[(8 + pxa) * DXP + q * 4];
            const int pbase = px0 + half * 16;
            const float ma = ms[pbase + pxa];
            const float mb = ms[pbase + 8 + pxa];
            const int off = half * 256 + pxa * 16 + q * 4;   // floats within row
            float4 xa = *(const float4*)&xrow[off];
            float4 xb = *(const float4*)&xrow[off + 128];
            float4 ra, rb;
            ra.x = xa.x + da.x * ma; ra.y = xa.y + da.y * ma;
            ra.z = xa.z + da.z * ma; ra.w = xa.w + da.w * ma;
            rb.x = xb.x + db.x * mb; rb.y = xb.y + db.y * mb;
            rb.z = xb.z + db.z * mb; rb.w = xb.w + db.w * mb;
            *(float4*)&orow[off]       = ra;
            *(float4*)&orow[off + 128] = rb;
        }
        __syncwarp();   // protect dxw reuse by next pass
    }
}

extern "C" void kernel_launch(void* const* d_in, const int* in_sizes, int n_in,
                              void* d_out, int out_size)
{
    const float* x  = (const float*)d_in[0];
    const float* w1 = (const float*)d_in[1];
    const float* b1 = (const float*)d_in[2];
    const float* w2 = (const float*)d_in[3];
    const float* b2 = (const float*)d_in[4];
    const float* w3 = (const float*)d_in[5];
    const float* b3 = (const float*)d_in[6];
    const uint32_t* mask = (const uint32_t*)d_in[7];
    float* out = (float*)d_out;

    cudaFuncSetAttribute(nca_step_kernel,
                         cudaFuncAttributeMaxDynamicSharedMemorySize, SMEM_BYTES);
    dim3 grid(HW / TW, HW / TH, 16);
    nca_step_kernel<<<grid, 256, SMEM_BYTES>>>(x, w1, b1, w2, b2, w3, b3, mask, out);
}